// round 12
// baseline (speedup 1.0000x reference)
#include <cuda_runtime.h>

// NonMaximaSuppression2d: x (8,32,512,512) fp32.
// m = max over 8 neighbors (replicate pad), floored at 0 (zeroed center tap).
// out = x * (x > m).
// R11: R9 body (6-row front batch, inline edge scalars, plain stores) +
//  (a) launch_bounds(128,13): 39-reg cap -> 13 CTAs/SM, n_conc=1924,
//      grid 32768 = 17.03 waves (near-integer; R9 was 18.45 @ 12/SM),
//  (b) front batch reordered: 6 vector LDG.128 first, then the 12 edge
//      scalars (they coalesce onto in-flight lines).
// R10 shuffle variant rejected: issue 55% (SHFL warp-collective cost > L1
// wavefront relief; L1 was not binding).

#define HH 512
#define WW 512
#define RPT 4           // rows per output strip
#define NROWS (RPT + 2) // 6 rows in the window
#define TPB 128         // threads per block = WW/4 float4 groups

__device__ __forceinline__ int clampy(int y) { return min(max(y, 0), HH - 1); }

// max of 3 horizontally adjacent values per lane (rows above/below)
__device__ __forceinline__ float4 hmax3(const float4& v, float l, float r) {
    float4 h;
    h.x = fmaxf(fmaxf(l,   v.x), v.y);
    h.y = fmaxf(fmaxf(v.x, v.y), v.z);
    h.z = fmaxf(fmaxf(v.y, v.z), v.w);
    h.w = fmaxf(fmaxf(v.z, v.w), r);
    return h;
}

// max of the 2 horizontal neighbors (center excluded; for the center row)
__device__ __forceinline__ float4 hmax2(const float4& v, float l, float r) {
    float4 h;
    h.x = fmaxf(l,   v.y);
    h.y = fmaxf(v.x, v.z);
    h.z = fmaxf(v.y, v.w);
    h.w = fmaxf(v.z, r);
    return h;
}

__global__ __launch_bounds__(TPB, 13)
void nms2d_kernel(const float* __restrict__ x, float* __restrict__ out) {
    const int tiles_per_img = HH / RPT;             // 128
    const int img  = blockIdx.x / tiles_per_img;
    const int tile = blockIdx.x % tiles_per_img;

    const float* in = x   + (size_t)img * HH * WW;
    float*       o  = out + (size_t)img * HH * WW;

    const int c  = threadIdx.x * 4;                 // 0..508
    const int y0 = tile * RPT;

    // phase 1: 6 independent vector loads, front-batched (DRAM-missing)
    float4 v[NROWS];
    #pragma unroll
    for (int k = 0; k < NROWS; k++)
        v[k] = *reinterpret_cast<const float4*>(
            in + (size_t)clampy(y0 - 1 + k) * WW + c);

    // phase 2: edge scalars — coalesce onto the in-flight lines above
    float l[NROWS], r[NROWS];
    #pragma unroll
    for (int k = 0; k < NROWS; k++) {
        const float* p = in + (size_t)clampy(y0 - 1 + k) * WW + c;
        l[k] = (c > 0)      ? __ldg(p - 1) : v[k].x;
        r[k] = (c + 4 < WW) ? __ldg(p + 4) : v[k].w;
    }

    float* op = o + (size_t)y0 * WW + c;

    #pragma unroll
    for (int i = 0; i < RPT; i++) {
        float4 mp = hmax3(v[i],     l[i],     r[i]);
        float4 mc = hmax2(v[i + 1], l[i + 1], r[i + 1]);
        float4 mn = hmax3(v[i + 2], l[i + 2], r[i + 2]);

        // fold the zeroed-center-tap floor (reference inits max at 0)
        float4 m;
        m.x = fmaxf(fmaxf(fmaxf(mp.x, mc.x), mn.x), 0.0f);
        m.y = fmaxf(fmaxf(fmaxf(mp.y, mc.y), mn.y), 0.0f);
        m.z = fmaxf(fmaxf(fmaxf(mp.z, mc.z), mn.z), 0.0f);
        m.w = fmaxf(fmaxf(fmaxf(mp.w, mc.w), mn.w), 0.0f);

        float4 xc = v[i + 1];
        float4 rr;
        rr.x = (xc.x > m.x) ? xc.x : 0.0f;
        rr.y = (xc.y > m.y) ? xc.y : 0.0f;
        rr.z = (xc.z > m.z) ? xc.z : 0.0f;
        rr.w = (xc.w > m.w) ? xc.w : 0.0f;

        *reinterpret_cast<float4*>(op) = rr;
        op += WW;
    }
}

extern "C" void kernel_launch(void* const* d_in, const int* in_sizes, int n_in,
                              void* d_out, int out_size) {
    const float* x = (const float*)d_in[0];
    float* out = (float*)d_out;

    const int n_img = in_sizes[0] / (HH * WW);      // B*C = 256
    const int blocks = n_img * (HH / RPT);          // 32768

    nms2d_kernel<<<blocks, TPB>>>(x, out);
}